// round 3
// baseline (speedup 1.0000x reference)
#include <cuda_runtime.h>

// ---------------- problem constants ----------------
constexpr int B_ = 8;
constexpr int NOBJ = 128;
constexpr int T_ = 12;
constexpr int MC = 2048;
constexpr int E_ = 128;          // EMBED_DIM
constexpr int ID_ = 64;          // IDENTITY_DIM
constexpr int AT_ = 64;          // ATTENTION_DIM
constexpr int H_ = 256;          // HIDDEN_DIM
constexpr int C_ = MC + NOBJ;    // 2176
constexpr int KSPLIT = 4;

// ---------------- device scratch ----------------
__device__ float g_dendron[B_ * C_ * E_];
__device__ float g_axon[B_ * C_ * E_];
__device__ float g_ia[B_ * C_ * 128];         // [0:64)=identity, [64:128)=attention (state)
__device__ float g_am[B_ * C_];               // attention row-means (for CURRENT step's tmp)
__device__ float g_tmp[B_ * KSPLIT * 128 * 128];
__device__ float g_M1[B_ * 128 * H_];         // (tmp @ w1^T)/C   layout [b][e][j]
__device__ float g_Mg[B_ * 128 * AT_];        // tmp[:,64:128]/C  layout [b][e][a]
__device__ float g_meta[T_ * B_ * AT_];
__device__ float g_proj[T_ * B_ * C_];
__device__ float g_args[B_ * T_ * E_];
__device__ float g_w1t[E_ * H_];              // axon w1 transposed: [k][j]
__device__ float g_w2t[H_ * AT_];             // axon w2 transposed: [k][j]

// ---------------- build dendron/axon/identity + init attention + init am ----------------
__global__ void k_build(const int* __restrict__ scene,
                        const float* __restrict__ aein, const float* __restrict__ aeout,
                        const float* __restrict__ aeid,
                        const float* __restrict__ cein, const float* __restrict__ ceout,
                        const float* __restrict__ ceid,
                        const float* __restrict__ att_init) {
    int c = blockIdx.x, b = blockIdx.y, d = threadIdx.x;  // d in [0,128)
    float din, ax, idv = 0.f;
    if (c < MC) {
        din = cein[c * E_ + d];
        ax = ceout[c * E_ + d];
        if (d < ID_) idv = ceid[c * ID_ + d];
    } else {
        int o = c - MC;
        float s_in = 0.f, s_out = 0.f, s_id = 0.f;
        #pragma unroll
        for (int a = 0; a < 4; a++) {
            int idx = scene[(b * NOBJ + o) * 4 + a];
            if (idx != -1) {
                s_in += aein[(idx + 1) * E_ + d];
                s_out += aeout[(idx + 1) * E_ + d];
                if (d < ID_) s_id += aeid[(idx + 1) * ID_ + d];
            }
        }
        din = s_in; ax = s_out; idv = s_id;
    }
    long off = (long)(b * C_ + c);
    g_dendron[off * E_ + d] = din;
    g_axon[off * E_ + d] = ax;
    if (d < ID_) g_ia[off * 128 + d] = idv;
    else         g_ia[off * 128 + d] = att_init[d - ID_];
    if (d == 0) {
        float s = 0.f;
        #pragma unroll
        for (int a = 0; a < AT_; a++) s += att_init[a];
        g_am[off] = s * (1.f / (float)AT_);
    }
}

// ---------------- transpose axon MLP weights ----------------
__global__ void k_wt(const float* __restrict__ w1, const float* __restrict__ w2) {
    int tid = blockIdx.x * 256 + threadIdx.x;
    for (int i = tid; i < H_ * E_; i += gridDim.x * 256) {
        int j = i / E_, k = i % E_;
        g_w1t[k * H_ + j] = w1[i];
    }
    for (int i = tid; i < AT_ * H_; i += gridDim.x * 256) {
        int j = i / H_, k = i % H_;
        g_w2t[k * AT_ + j] = w2[i];
    }
}

// ---------------- gather arguments + meta recurrence (per-batch block) ----------------
__global__ void k_args_meta(const int* __restrict__ parg, const int* __restrict__ pop,
                            const float* __restrict__ ceout, const float* __restrict__ att_init,
                            const float* __restrict__ mw1, const float* __restrict__ mb1,
                            const float* __restrict__ mw2, const float* __restrict__ mb2) {
    int b = blockIdx.x;
    int tid = threadIdx.x;
    __shared__ float meta_s[AT_];
    __shared__ float xbuf[E_ + AT_];
    __shared__ float hbuf[H_];

    for (int i = tid; i < T_ * E_; i += 256) {
        int t = i / E_, d = i % E_;
        g_args[(b * T_ + t) * E_ + d] = ceout[parg[b * T_ + t] * E_ + d];
    }
    if (tid < AT_) meta_s[tid] = att_init[tid];
    __syncthreads();

    for (int t = 0; t < T_; t++) {
        if (tid < AT_) xbuf[tid] = meta_s[tid];
        else if (tid < AT_ + E_) xbuf[tid] = g_args[(b * T_ + t) * E_ + tid - AT_];
        __syncthreads();
        float acc = mb1[tid];
        #pragma unroll 4
        for (int k = 0; k < AT_ + E_; k++) acc += xbuf[k] * mw1[tid * (AT_ + E_) + k];
        hbuf[tid] = fmaxf(acc, 0.f);
        __syncthreads();
        if (tid < AT_) {
            float o = mb2[tid];
            #pragma unroll 4
            for (int k = 0; k < H_; k++) o += hbuf[k] * mw2[tid * H_ + k];
            float m = (pop[b * T_ + t] == 0) ? 1.f : 0.f;
            float nv = m * o + (1.f - m) * meta_s[tid];
            meta_s[tid] = nv;
            g_meta[(t * B_ + b) * AT_ + tid] = nv;
        }
        __syncthreads();
    }
}

// ---------------- proj[t,b,c] for all t at once (axon read once) ----------------
// block = 256 threads = 8 warps = 8 rows; grid = B*C/8
__global__ void k_projA() {
    __shared__ float sargs[T_ * E_];
    int blk = blockIdx.x;
    int tid = threadIdx.x;
    int row0 = blk * 8;
    int b = row0 / C_;
    for (int i = tid; i < T_ * E_; i += 256) sargs[i] = g_args[b * T_ * E_ + i];
    __syncthreads();
    int w = tid >> 5, lane = tid & 31;
    int row = row0 + w;
    int c = row % C_;
    const float* ax = &g_axon[(long)row * E_];
    float a0 = ax[lane], a1 = ax[lane + 32], a2 = ax[lane + 64], a3 = ax[lane + 96];
    #pragma unroll
    for (int t = 0; t < T_; t++) {
        float s = a0 * sargs[t * E_ + lane] + a1 * sargs[t * E_ + lane + 32]
                + a2 * sargs[t * E_ + lane + 64] + a3 * sargs[t * E_ + lane + 96];
        #pragma unroll
        for (int o = 16; o; o >>= 1) s += __shfl_xor_sync(0xffffffffu, s, o);
        if (lane == 0) g_proj[(t * B_ + b) * C_ + c] = s * (1.f / (float)E_);
    }
}

// ---------------- ins_hist (all timesteps at once) ----------------
__global__ void k_ins(float* __restrict__ out_ins) {
    int idx = blockIdx.x * 256 + threadIdx.x;
    int a = idx & (AT_ - 1);
    int rest = idx >> 6;
    int c = rest % C_;
    int tb = rest / C_;
    out_ins[idx] = g_meta[tb * AT_ + a] * g_proj[tb * C_ + c];
}

// ---------------- tmp[e,d] = sum_c (am[c]*axon[c,e]) * ia[c,d],  K-split by 4 ----------------
// grid (2,2,B*4); block 256; 64x64 tile, 4x4 per thread
__global__ void k_tmp() {
    __shared__ float sA[32][64];
    __shared__ float sB[32][64];
    int et = blockIdx.x * 64, dt = blockIdx.y * 64;
    int b = blockIdx.z >> 2, kc = blockIdx.z & 3;
    int cbase = kc * (C_ / KSPLIT);              // 544
    int tid = threadIdx.x;
    int ty = tid >> 4, tx = tid & 15;
    float acc[4][4];
    #pragma unroll
    for (int i = 0; i < 4; i++)
        #pragma unroll
        for (int j = 0; j < 4; j++) acc[i][j] = 0.f;

    for (int ct = 0; ct < C_ / KSPLIT; ct += 32) {
        #pragma unroll
        for (int r = 0; r < 2; r++) {
            int rowk = (tid >> 4) + r * 16;
            int colg = (tid & 15) * 4;
            int c = cbase + ct + rowk;
            long base = (long)(b * C_ + c);
            float amv = g_am[base];
            float4 av = *(const float4*)&g_axon[base * E_ + et + colg];
            float4 bv = *(const float4*)&g_ia[base * 128 + dt + colg];
            sA[rowk][colg + 0] = av.x * amv;
            sA[rowk][colg + 1] = av.y * amv;
            sA[rowk][colg + 2] = av.z * amv;
            sA[rowk][colg + 3] = av.w * amv;
            *(float4*)&sB[rowk][colg] = bv;
        }
        __syncthreads();
        #pragma unroll
        for (int k = 0; k < 32; k++) {
            float xa[4], yb[4];
            #pragma unroll
            for (int i = 0; i < 4; i++) xa[i] = sA[k][ty + 16 * i];
            #pragma unroll
            for (int j = 0; j < 4; j++) yb[j] = sB[k][tx + 16 * j];
            #pragma unroll
            for (int i = 0; i < 4; i++)
                #pragma unroll
                for (int j = 0; j < 4; j++) acc[i][j] += xa[i] * yb[j];
        }
        __syncthreads();
    }
    float* o = &g_tmp[(long)(b * KSPLIT + kc) * 16384];
    #pragma unroll
    for (int i = 0; i < 4; i++)
        #pragma unroll
        for (int j = 0; j < 4; j++)
            o[(et + ty + 16 * i) * 128 + dt + tx + 16 * j] = acc[i][j];
}

// ---------------- M1 = tmpsum @ w1^T / C ;  Mg = tmpsum[:,64:128]/C ----------------
// grid (8, B); block 256: 16 e-rows per block
__global__ void k_small() {
    __shared__ float ts[16][128];
    int b = blockIdx.y;
    int er0 = blockIdx.x * 16;
    int tid = threadIdx.x;
    for (int i = tid; i < 16 * 128; i += 256) {
        int r = i >> 7, k = i & 127;
        long base = (long)b * KSPLIT * 16384 + (er0 + r) * 128 + k;
        float s = g_tmp[base] + g_tmp[base + 16384] + g_tmp[base + 32768] + g_tmp[base + 49152];
        ts[r][k] = s;
    }
    __syncthreads();
    const float sc = 1.f / (float)C_;
    int j = tid;  // 0..255
    float acc[16];
    #pragma unroll
    for (int r = 0; r < 16; r++) acc[r] = 0.f;
    for (int k = 0; k < 128; k++) {
        float w = g_w1t[k * H_ + j];
        #pragma unroll
        for (int r = 0; r < 16; r++) acc[r] += ts[r][k] * w;
    }
    #pragma unroll
    for (int r = 0; r < 16; r++)
        g_M1[((long)b * 128 + er0 + r) * H_ + j] = acc[r] * sc;
    for (int i = tid; i < 16 * AT_; i += 256) {
        int r = i >> 6, a = i & 63;
        g_Mg[((long)b * 128 + er0 + r) * AT_ + a] = ts[r][ID_ + a] * sc;
    }
}

// ---------------- fused: h=relu(d@M1+b1); out=h@w2t+b2; resid=d@Mg; update+hist+next am ----
// grid (17, B); block 512; dynamic smem: M1 128KB + Mg 32KB
__global__ void __launch_bounds__(512, 1)
k_fused(int t, const int* __restrict__ pop,
        const float* __restrict__ b1v, const float* __restrict__ b2v,
        float* __restrict__ att_hist, float* __restrict__ trans_hist) {
    extern __shared__ float sm[];
    float* sM1 = sm;                  // [128][256]
    float* sMg = sm + 128 * H_;       // [128][64]
    __shared__ __align__(16) float ds[16][128];
    __shared__ __align__(16) float hs[16][256];
    __shared__ float s_rowsum[16];

    int b = blockIdx.y;
    int tid = threadIdx.x;

    {   // stage per-batch matrices
        const float4* p = (const float4*)&g_M1[(long)b * 128 * H_];
        float4* d4 = (float4*)sM1;
        for (int i = tid; i < 128 * H_ / 4; i += 512) d4[i] = p[i];
        const float4* pg = (const float4*)&g_Mg[(long)b * 128 * AT_];
        float4* dg = (float4*)sMg;
        for (int i = tid; i < 128 * AT_ / 4; i += 512) dg[i] = pg[i];
    }

    int j = tid & 255, half = tid >> 8;        // layer1: 256 outputs, 2 row-halves
    int j2 = tid & 63, rr = tid >> 6;          // layer2: 64 outputs, rows rr & rr+8
    int r0 = half * 8;

    float bb1 = b1v[j];
    float bb2 = b2v[j2];
    int op = pop[b * T_ + t];
    float insv = (op == 1) ? 1.f : 0.f;
    float trv = (op == 2) ? 1.f : 0.f;
    float metav = g_meta[(t * B_ + b) * AT_ + j2];

    int c0base = blockIdx.x * 128;

    for (int g = 0; g < 8; g++) {
        int c0 = c0base + g * 16;
        __syncthreads();
        {   // stage 16 dendron rows (2048 floats, 1 float4 each)
            const float4* p = (const float4*)&g_dendron[((long)(b * C_ + c0)) * E_];
            ((float4*)&ds[0][0])[tid] = p[tid];
        }
        if (tid < 16) s_rowsum[tid] = 0.f;
        __syncthreads();

        // ---- layer 1 ----
        float acc[8];
        #pragma unroll
        for (int r = 0; r < 8; r++) acc[r] = bb1;
        for (int k = 0; k < 128; k += 4) {
            float w0 = sM1[(k + 0) * H_ + j];
            float w1 = sM1[(k + 1) * H_ + j];
            float w2 = sM1[(k + 2) * H_ + j];
            float w3 = sM1[(k + 3) * H_ + j];
            #pragma unroll
            for (int r = 0; r < 8; r++) {
                float4 dv = *(const float4*)&ds[r0 + r][k];
                acc[r] += dv.x * w0 + dv.y * w1 + dv.z * w2 + dv.w * w3;
            }
        }
        #pragma unroll
        for (int r = 0; r < 8; r++) hs[r0 + r][j] = fmaxf(acc[r], 0.f);
        __syncthreads();

        // ---- layer 2 (rows rr, rr+8) ----
        float o0 = bb2, o1 = bb2;
        for (int k = 0; k < 256; k += 4) {
            float w0 = g_w2t[(k + 0) * AT_ + j2];
            float w1 = g_w2t[(k + 1) * AT_ + j2];
            float w2 = g_w2t[(k + 2) * AT_ + j2];
            float w3 = g_w2t[(k + 3) * AT_ + j2];
            float4 ha = *(const float4*)&hs[rr][k];
            float4 hb = *(const float4*)&hs[rr + 8][k];
            o0 += ha.x * w0 + ha.y * w1 + ha.z * w2 + ha.w * w3;
            o1 += hb.x * w0 + hb.y * w1 + hb.z * w2 + hb.w * w3;
        }

        // ---- residual resid = d @ Mg ----
        float ra0 = 0.f, ra1 = 0.f;
        for (int k = 0; k < 128; k += 4) {
            float w0 = sMg[(k + 0) * AT_ + j2];
            float w1 = sMg[(k + 1) * AT_ + j2];
            float w2 = sMg[(k + 2) * AT_ + j2];
            float w3 = sMg[(k + 3) * AT_ + j2];
            float4 da = *(const float4*)&ds[rr][k];
            float4 db = *(const float4*)&ds[rr + 8][k];
            ra0 += da.x * w0 + da.y * w1 + da.z * w2 + da.w * w3;
            ra1 += db.x * w0 + db.y * w1 + db.z * w2 + db.w * w3;
        }

        // ---- update + history + row-sum for next am ----
        float asum0 = 0.f, asum1 = 0.f;
        #pragma unroll
        for (int p = 0; p < 2; p++) {
            int r = (p == 0) ? rr : rr + 8;
            float transfer = ((p == 0) ? o0 : o1) + ((p == 0) ? ra0 : ra1);
            int c = c0 + r;
            long bc = (long)(b * C_ + c);
            float insert = metav * g_proj[(t * B_ + b) * C_ + c];
            float a = g_ia[bc * 128 + ID_ + j2];
            a += insv * insert + trv * transfer;
            a = (a >= 0.f) ? a : 0.01f * a;
            a = fminf(fmaxf(a, -1.f), 2.f);
            g_ia[bc * 128 + ID_ + j2] = a;
            long hidx = (((long)t * B_ + b) * C_ + c) * AT_ + j2;
            att_hist[hidx] = a;
            trans_hist[hidx] = transfer;
            if (p == 0) asum0 = a; else asum1 = a;
        }
        // warp reduce (rr constant within warp)
        #pragma unroll
        for (int o = 16; o; o >>= 1) {
            asum0 += __shfl_xor_sync(0xffffffffu, asum0, o);
            asum1 += __shfl_xor_sync(0xffffffffu, asum1, o);
        }
        if ((tid & 31) == 0) {
            atomicAdd(&s_rowsum[rr], asum0);
            atomicAdd(&s_rowsum[rr + 8], asum1);
        }
        __syncthreads();
        if (tid < 16)
            g_am[(long)b * C_ + c0 + tid] = s_rowsum[tid] * (1.f / (float)AT_);
    }
}

// ---------------- final log-softmax over C of mean attention ----------------
__global__ void k_final(float* __restrict__ out) {
    int b = blockIdx.x, tid = threadIdx.x;
    __shared__ float m_s[C_];
    __shared__ float red[256];
    for (int c = tid; c < C_; c += 256) {
        // g_am already holds the mean of the final attention
        m_s[c] = g_am[(long)b * C_ + c];
    }
    __syncthreads();
    float mx = -1e30f;
    for (int c = tid; c < C_; c += 256) mx = fmaxf(mx, m_s[c]);
    red[tid] = mx;
    __syncthreads();
    for (int s = 128; s; s >>= 1) {
        if (tid < s) red[tid] = fmaxf(red[tid], red[tid + s]);
        __syncthreads();
    }
    mx = red[0];
    __syncthreads();
    float se = 0.f;
    for (int c = tid; c < C_; c += 256) se += expf(m_s[c] - mx);
    red[tid] = se;
    __syncthreads();
    for (int s = 128; s; s >>= 1) {
        if (tid < s) red[tid] += red[tid + s];
        __syncthreads();
    }
    float lse = logf(red[0]);
    __syncthreads();
    for (int c = tid; c < C_; c += 256) out[b * C_ + c] = m_s[c] - mx - lse;
}

// ---------------- launch ----------------
extern "C" void kernel_launch(void* const* d_in, const int* in_sizes, int n_in,
                              void* d_out, int out_size) {
    (void)in_sizes; (void)n_in; (void)out_size;
    const int* scene     = (const int*)d_in[0];
    const int* prog_op   = (const int*)d_in[1];
    const int* prog_arg  = (const int*)d_in[2];
    const float* aein    = (const float*)d_in[3];
    const float* aeout   = (const float*)d_in[4];
    const float* aeid    = (const float*)d_in[5];
    const float* cein    = (const float*)d_in[6];
    const float* ceout   = (const float*)d_in[7];
    const float* ceid    = (const float*)d_in[8];
    const float* att_init = (const float*)d_in[11];
    const float* axw1    = (const float*)d_in[12];
    const float* axb1    = (const float*)d_in[13];
    const float* axw2    = (const float*)d_in[14];
    const float* axb2    = (const float*)d_in[15];
    const float* mw1     = (const float*)d_in[16];
    const float* mb1     = (const float*)d_in[17];
    const float* mw2     = (const float*)d_in[18];
    const float* mb2     = (const float*)d_in[19];

    float* out = (float*)d_out;
    float* att_hist = out + B_ * C_;
    float* ins_hist = att_hist + (long)T_ * B_ * C_ * AT_;
    float* trans_hist = ins_hist + (long)T_ * B_ * C_ * AT_;

    const size_t dsm = (size_t)(128 * H_ + 128 * AT_) * 4;   // 160 KB
    cudaFuncSetAttribute(k_fused, cudaFuncAttributeMaxDynamicSharedMemorySize, (int)dsm);

    k_wt<<<64, 256>>>(axw1, axw2);
    k_build<<<dim3(C_, B_), 128>>>(scene, aein, aeout, aeid, cein, ceout, ceid, att_init);
    k_args_meta<<<B_, 256>>>(prog_arg, prog_op, ceout, att_init, mw1, mb1, mw2, mb2);
    k_projA<<<B_ * C_ / 8, 256>>>();
    k_ins<<<(T_ * B_ * C_ * AT_) / 256, 256>>>(ins_hist);

    for (int t = 0; t < T_; t++) {
        k_tmp<<<dim3(2, 2, B_ * KSPLIT), 256>>>();
        k_small<<<dim3(8, B_), 256>>>();
        k_fused<<<dim3(C_ / 128, B_), 512, dsm>>>(t, prog_op, axb1, axb2, att_hist, trans_hist);
    }
    k_final<<<B_, 256>>>(out);
}

// round 4
// speedup vs baseline: 2.0394x; 2.0394x over previous
#include <cuda_runtime.h>

// ---------------- problem constants ----------------
constexpr int B_ = 8;
constexpr int NOBJ = 128;
constexpr int T_ = 12;
constexpr int MC = 2048;
constexpr int E_ = 128;          // EMBED_DIM
constexpr int ID_ = 64;          // IDENTITY_DIM
constexpr int AT_ = 64;          // ATTENTION_DIM
constexpr int H_ = 256;          // HIDDEN_DIM
constexpr int C_ = MC + NOBJ;    // 2176
constexpr int KSPLIT = 17;       // 2176 / 17 = 128 rows per K-chunk

// ---------------- device scratch ----------------
__device__ float g_dendron[B_ * C_ * E_];
__device__ float g_axon[B_ * C_ * E_];
__device__ float g_ia[B_ * C_ * 128];            // [0:64)=identity, [64:128)=attention (state)
__device__ float g_am[B_ * C_];                  // attention row-means for CURRENT step
__device__ float g_tmp[B_ * KSPLIT * 128 * 128]; // K-split partials
__device__ float g_M1[B_ * 128 * H_];            // (tmp @ w1^T)/C   layout [b][e][j]
__device__ float g_Mg[B_ * 128 * AT_];           // tmp[:,64:128]/C  layout [b][e][a]
__device__ float g_meta[T_ * B_ * AT_];
__device__ float g_proj[T_ * B_ * C_];
__device__ float g_args[B_ * T_ * E_];
__device__ float g_w1t[E_ * H_];                 // axon w1 transposed: [k][j]
__device__ float g_w2t[H_ * AT_];                // axon w2 transposed: [k][j]

// ---------------- tf32 helpers ----------------
__device__ __forceinline__ unsigned f2tf(float x) {
    unsigned r;
    asm("cvt.rna.tf32.f32 %0, %1;" : "=r"(r) : "f"(x));
    return r;
}

__device__ __forceinline__ void mma8(float* d, const unsigned* a, const unsigned* b) {
    asm("mma.sync.aligned.m16n8k8.row.col.f32.tf32.tf32.f32 "
        "{%0,%1,%2,%3},{%4,%5,%6,%7},{%8,%9},{%0,%1,%2,%3};"
        : "+f"(d[0]), "+f"(d[1]), "+f"(d[2]), "+f"(d[3])
        : "r"(a[0]), "r"(a[1]), "r"(a[2]), "r"(a[3]), "r"(b[0]), "r"(b[1]));
}

// ---------------- build dendron/axon/identity + init attention + init am ----------------
__global__ void k_build(const int* __restrict__ scene,
                        const float* __restrict__ aein, const float* __restrict__ aeout,
                        const float* __restrict__ aeid,
                        const float* __restrict__ cein, const float* __restrict__ ceout,
                        const float* __restrict__ ceid,
                        const float* __restrict__ att_init) {
    int c = blockIdx.x, b = blockIdx.y, d = threadIdx.x;  // d in [0,128)
    float din, ax, idv = 0.f;
    if (c < MC) {
        din = cein[c * E_ + d];
        ax = ceout[c * E_ + d];
        if (d < ID_) idv = ceid[c * ID_ + d];
    } else {
        int o = c - MC;
        float s_in = 0.f, s_out = 0.f, s_id = 0.f;
        #pragma unroll
        for (int a = 0; a < 4; a++) {
            int idx = scene[(b * NOBJ + o) * 4 + a];
            if (idx != -1) {
                s_in += aein[(idx + 1) * E_ + d];
                s_out += aeout[(idx + 1) * E_ + d];
                if (d < ID_) s_id += aeid[(idx + 1) * ID_ + d];
            }
        }
        din = s_in; ax = s_out; idv = s_id;
    }
    long off = (long)(b * C_ + c);
    g_dendron[off * E_ + d] = din;
    g_axon[off * E_ + d] = ax;
    if (d < ID_) g_ia[off * 128 + d] = idv;
    else         g_ia[off * 128 + d] = att_init[d - ID_];
    if (d == 0) {
        float s = 0.f;
        #pragma unroll
        for (int a = 0; a < AT_; a++) s += att_init[a];
        g_am[off] = s * (1.f / (float)AT_);
    }
}

// ---------------- transpose axon MLP weights ----------------
__global__ void k_wt(const float* __restrict__ w1, const float* __restrict__ w2) {
    int tid = blockIdx.x * 256 + threadIdx.x;
    for (int i = tid; i < H_ * E_; i += gridDim.x * 256) {
        int j = i / E_, k = i % E_;
        g_w1t[k * H_ + j] = w1[i];
    }
    for (int i = tid; i < AT_ * H_; i += gridDim.x * 256) {
        int j = i / H_, k = i % H_;
        g_w2t[k * AT_ + j] = w2[i];
    }
}

// ---------------- gather arguments + meta recurrence (per-batch block) ----------------
__global__ void k_args_meta(const int* __restrict__ parg, const int* __restrict__ pop,
                            const float* __restrict__ ceout, const float* __restrict__ att_init,
                            const float* __restrict__ mw1, const float* __restrict__ mb1,
                            const float* __restrict__ mw2, const float* __restrict__ mb2) {
    int b = blockIdx.x;
    int tid = threadIdx.x;
    __shared__ float meta_s[AT_];
    __shared__ float xbuf[E_ + AT_];
    __shared__ float hbuf[H_];

    for (int i = tid; i < T_ * E_; i += 256) {
        int t = i / E_, d = i % E_;
        g_args[(b * T_ + t) * E_ + d] = ceout[parg[b * T_ + t] * E_ + d];
    }
    if (tid < AT_) meta_s[tid] = att_init[tid];
    __syncthreads();

    for (int t = 0; t < T_; t++) {
        if (tid < AT_) xbuf[tid] = meta_s[tid];
        else if (tid < AT_ + E_) xbuf[tid] = g_args[(b * T_ + t) * E_ + tid - AT_];
        __syncthreads();
        float acc = mb1[tid];
        #pragma unroll 4
        for (int k = 0; k < AT_ + E_; k++) acc += xbuf[k] * mw1[tid * (AT_ + E_) + k];
        hbuf[tid] = fmaxf(acc, 0.f);
        __syncthreads();
        if (tid < AT_) {
            float o = mb2[tid];
            #pragma unroll 4
            for (int k = 0; k < H_; k++) o += hbuf[k] * mw2[tid * H_ + k];
            float m = (pop[b * T_ + t] == 0) ? 1.f : 0.f;
            float nv = m * o + (1.f - m) * meta_s[tid];
            meta_s[tid] = nv;
            g_meta[(t * B_ + b) * AT_ + tid] = nv;
        }
        __syncthreads();
    }
}

// ---------------- proj[t,b,c] for all t at once ----------------
__global__ void k_projA() {
    __shared__ float sargs[T_ * E_];
    int blk = blockIdx.x;
    int tid = threadIdx.x;
    int row0 = blk * 8;
    int b = row0 / C_;
    for (int i = tid; i < T_ * E_; i += 256) sargs[i] = g_args[b * T_ * E_ + i];
    __syncthreads();
    int w = tid >> 5, lane = tid & 31;
    int row = row0 + w;
    int c = row % C_;
    const float* ax = &g_axon[(long)row * E_];
    float a0 = ax[lane], a1 = ax[lane + 32], a2 = ax[lane + 64], a3 = ax[lane + 96];
    #pragma unroll
    for (int t = 0; t < T_; t++) {
        float s = a0 * sargs[t * E_ + lane] + a1 * sargs[t * E_ + lane + 32]
                + a2 * sargs[t * E_ + lane + 64] + a3 * sargs[t * E_ + lane + 96];
        #pragma unroll
        for (int o = 16; o; o >>= 1) s += __shfl_xor_sync(0xffffffffu, s, o);
        if (lane == 0) g_proj[(t * B_ + b) * C_ + c] = s * (1.f / (float)E_);
    }
}

// ---------------- ins_hist (all timesteps at once) ----------------
__global__ void k_ins(float* __restrict__ out_ins) {
    int idx = blockIdx.x * 256 + threadIdx.x;
    int a = idx & (AT_ - 1);
    int rest = idx >> 6;
    int c = rest % C_;
    int tb = rest / C_;
    out_ins[idx] = g_meta[tb * AT_ + a] * g_proj[tb * C_ + c];
}

// ---------------- tf32 MMA: tmp[e,d] = sum_c (am[c]*axon[c,e]) * ia[c,d], K-split by 17 ----
// grid (17, B); block 256 (8 warps); each warp: 16 e-rows x 128 d
__global__ void __launch_bounds__(256, 1) k_tmp_tc() {
    __shared__ unsigned sA[32][136];   // (am*axon)[c][e] tf32
    __shared__ unsigned sB[32][136];   // ia[c][d] tf32
    int kc = blockIdx.x, b = blockIdx.y;
    int cbase = kc * 128;
    int tid = threadIdx.x, w = tid >> 5, lane = tid & 31;
    int grp = lane >> 2, thr = lane & 3;
    int e0 = w * 16;

    float acc[16][4];
    #pragma unroll
    for (int n = 0; n < 16; n++)
        #pragma unroll
        for (int q = 0; q < 4; q++) acc[n][q] = 0.f;

    for (int it = 0; it < 4; it++) {
        __syncthreads();
        for (int i = tid; i < 32 * 32; i += 256) {
            int r = i >> 5, q = (i & 31) * 4;
            int c = cbase + it * 32 + r;
            long base = (long)(b * C_ + c);
            float amv = g_am[base];
            float4 av = *(const float4*)&g_axon[base * E_ + q];
            sA[r][q + 0] = f2tf(av.x * amv);
            sA[r][q + 1] = f2tf(av.y * amv);
            sA[r][q + 2] = f2tf(av.z * amv);
            sA[r][q + 3] = f2tf(av.w * amv);
            float4 bv = *(const float4*)&g_ia[base * 128 + q];
            sB[r][q + 0] = f2tf(bv.x);
            sB[r][q + 1] = f2tf(bv.y);
            sB[r][q + 2] = f2tf(bv.z);
            sB[r][q + 3] = f2tf(bv.w);
        }
        __syncthreads();
        #pragma unroll
        for (int ks = 0; ks < 4; ks++) {
            int kb = ks * 8;
            unsigned a[4];
            a[0] = sA[kb + thr][e0 + grp];
            a[1] = sA[kb + thr][e0 + grp + 8];
            a[2] = sA[kb + thr + 4][e0 + grp];
            a[3] = sA[kb + thr + 4][e0 + grp + 8];
            #pragma unroll
            for (int n = 0; n < 16; n++) {
                unsigned bb[2] = { sB[kb + thr][n * 8 + grp],
                                   sB[kb + thr + 4][n * 8 + grp] };
                mma8(acc[n], a, bb);
            }
        }
    }
    float* o = &g_tmp[(long)(b * KSPLIT + kc) * 16384];
    #pragma unroll
    for (int n = 0; n < 16; n++) {
        int col = n * 8 + thr * 2;
        *(float2*)&o[(e0 + grp) * 128 + col]     = make_float2(acc[n][0], acc[n][1]);
        *(float2*)&o[(e0 + grp + 8) * 128 + col] = make_float2(acc[n][2], acc[n][3]);
    }
}

// ---------------- M1 = tmpsum @ w1^T / C ;  Mg = tmpsum[:,64:128]/C ----------------
// grid (8, B); block 256: 16 e-rows per block
__global__ void k_small() {
    __shared__ float ts[16][128];
    int b = blockIdx.y;
    int er0 = blockIdx.x * 16;
    int tid = threadIdx.x;
    for (int i = tid; i < 16 * 128; i += 256) {
        int r = i >> 7, k = i & 127;
        long base = (long)b * KSPLIT * 16384 + (er0 + r) * 128 + k;
        float s = 0.f;
        #pragma unroll
        for (int p = 0; p < KSPLIT; p++) s += g_tmp[base + (long)p * 16384];
        ts[r][k] = s;
    }
    __syncthreads();
    const float sc = 1.f / (float)C_;
    int j = tid;  // 0..255
    float acc[16];
    #pragma unroll
    for (int r = 0; r < 16; r++) acc[r] = 0.f;
    for (int k = 0; k < 128; k++) {
        float w = g_w1t[k * H_ + j];
        #pragma unroll
        for (int r = 0; r < 16; r++) acc[r] += ts[r][k] * w;
    }
    #pragma unroll
    for (int r = 0; r < 16; r++)
        g_M1[((long)b * 128 + er0 + r) * H_ + j] = acc[r] * sc;
    for (int i = tid; i < 16 * AT_; i += 256) {
        int r = i >> 6, a = i & 63;
        g_Mg[((long)b * 128 + er0 + r) * AT_ + a] = ts[r][ID_ + a] * sc;
    }
}

// ---------------- fused tf32 MMA: h=relu(d@M1+b1); out=h@w2t+b2 + d@Mg; update+hist+am ----
// grid (17, B); block 256 (8 warps), 128 c-rows per block, everything in smem
// dyn smem words: sD 128*132, sM1c 128*72, sHc 128*68, sW2c 64*72, sMg 128*72 = 48640 (190KB)
__global__ void __launch_bounds__(256, 1)
k_fused_tc(int t, const int* __restrict__ pop,
           const float* __restrict__ b1v, const float* __restrict__ b2v,
           float* __restrict__ att_hist, float* __restrict__ trans_hist) {
    extern __shared__ unsigned smem_u[];
    unsigned* sD   = smem_u;            // [128][132]  dendron tf32, A-layout (row, k=e)
    unsigned* sM1c = smem_u + 16896;    // [128][72]   M1 chunk (k=e, n=j)
    unsigned* sHc  = smem_u + 26112;    // [128][68]   h chunk (row, k=j)
    unsigned* sW2c = smem_u + 34816;    // [64][72]    w2t chunk (k=j, n=a)
    unsigned* sMg  = smem_u + 39424;    // [128][72]   Mg (k=e, n=a)
    __shared__ float s_b1[H_];
    __shared__ float s_b2[AT_];
    __shared__ float s_meta[AT_];

    int b = blockIdx.y;
    int c0 = blockIdx.x * 128;
    int tid = threadIdx.x, w = tid >> 5, lane = tid & 31;
    int grp = lane >> 2, thr = lane & 3;
    int r0 = w * 16;

    // stage sD and sMg (once)
    for (int i = tid; i < 128 * 32; i += 256) {
        int r = i >> 5, q = (i & 31) * 4;
        float4 v = *(const float4*)&g_dendron[((long)(b * C_ + c0 + r)) * E_ + q];
        unsigned* p = &sD[r * 132 + q];
        p[0] = f2tf(v.x); p[1] = f2tf(v.y); p[2] = f2tf(v.z); p[3] = f2tf(v.w);
    }
    for (int i = tid; i < 128 * 16; i += 256) {
        int r = i >> 4, q = (i & 15) * 4;
        float4 v = *(const float4*)&g_Mg[((long)b * 128 + r) * AT_ + q];
        unsigned* p = &sMg[r * 72 + q];
        p[0] = f2tf(v.x); p[1] = f2tf(v.y); p[2] = f2tf(v.z); p[3] = f2tf(v.w);
    }
    s_b1[tid] = b1v[tid];
    if (tid < AT_) {
        s_b2[tid] = b2v[tid];
        s_meta[tid] = g_meta[(t * B_ + b) * AT_ + tid];
    }

    float acc_o[8][4];
    #pragma unroll
    for (int n = 0; n < 8; n++)
        #pragma unroll
        for (int q = 0; q < 4; q++) acc_o[n][q] = 0.f;

    for (int nc = 0; nc < 4; nc++) {
        __syncthreads();
        // stage M1 chunk and w2t chunk
        for (int i = tid; i < 128 * 16; i += 256) {
            int r = i >> 4, q = (i & 15) * 4;
            float4 v = *(const float4*)&g_M1[((long)b * 128 + r) * H_ + nc * 64 + q];
            unsigned* p = &sM1c[r * 72 + q];
            p[0] = f2tf(v.x); p[1] = f2tf(v.y); p[2] = f2tf(v.z); p[3] = f2tf(v.w);
        }
        for (int i = tid; i < 64 * 16; i += 256) {
            int r = i >> 4, q = (i & 15) * 4;
            float4 v = *(const float4*)&g_w2t[(nc * 64 + r) * AT_ + q];
            unsigned* p = &sW2c[r * 72 + q];
            p[0] = f2tf(v.x); p[1] = f2tf(v.y); p[2] = f2tf(v.z); p[3] = f2tf(v.w);
        }
        __syncthreads();

        // ---- layer 1: 16 rows x 64 cols per warp, K=128 ----
        float acc_h[8][4];
        #pragma unroll
        for (int n = 0; n < 8; n++)
            #pragma unroll
            for (int q = 0; q < 4; q++) acc_h[n][q] = 0.f;
        #pragma unroll
        for (int ks = 0; ks < 16; ks++) {
            int kb = ks * 8;
            unsigned a[4];
            a[0] = sD[(r0 + grp) * 132 + kb + thr];
            a[1] = sD[(r0 + grp + 8) * 132 + kb + thr];
            a[2] = sD[(r0 + grp) * 132 + kb + thr + 4];
            a[3] = sD[(r0 + grp + 8) * 132 + kb + thr + 4];
            #pragma unroll
            for (int n = 0; n < 8; n++) {
                unsigned bb[2] = { sM1c[(kb + thr) * 72 + n * 8 + grp],
                                   sM1c[(kb + thr + 4) * 72 + n * 8 + grp] };
                mma8(acc_h[n], a, bb);
            }
        }
        // bias + relu + tf32 into sHc
        #pragma unroll
        for (int n = 0; n < 8; n++) {
            int col = n * 8 + thr * 2;
            float bias0 = s_b1[nc * 64 + col], bias1 = s_b1[nc * 64 + col + 1];
            sHc[(r0 + grp) * 68 + col]         = f2tf(fmaxf(acc_h[n][0] + bias0, 0.f));
            sHc[(r0 + grp) * 68 + col + 1]     = f2tf(fmaxf(acc_h[n][1] + bias1, 0.f));
            sHc[(r0 + grp + 8) * 68 + col]     = f2tf(fmaxf(acc_h[n][2] + bias0, 0.f));
            sHc[(r0 + grp + 8) * 68 + col + 1] = f2tf(fmaxf(acc_h[n][3] + bias1, 0.f));
        }
        __syncthreads();

        // ---- layer 2 partial: K=64 ----
        #pragma unroll
        for (int ks = 0; ks < 8; ks++) {
            int kb = ks * 8;
            unsigned a[4];
            a[0] = sHc[(r0 + grp) * 68 + kb + thr];
            a[1] = sHc[(r0 + grp + 8) * 68 + kb + thr];
            a[2] = sHc[(r0 + grp) * 68 + kb + thr + 4];
            a[3] = sHc[(r0 + grp + 8) * 68 + kb + thr + 4];
            #pragma unroll
            for (int n = 0; n < 8; n++) {
                unsigned bb[2] = { sW2c[(kb + thr) * 72 + n * 8 + grp],
                                   sW2c[(kb + thr + 4) * 72 + n * 8 + grp] };
                mma8(acc_o[n], a, bb);
            }
        }
    }

    // ---- residual: d @ Mg, K=128, into same accumulators ----
    #pragma unroll
    for (int ks = 0; ks < 16; ks++) {
        int kb = ks * 8;
        unsigned a[4];
        a[0] = sD[(r0 + grp) * 132 + kb + thr];
        a[1] = sD[(r0 + grp + 8) * 132 + kb + thr];
        a[2] = sD[(r0 + grp) * 132 + kb + thr + 4];
        a[3] = sD[(r0 + grp + 8) * 132 + kb + thr + 4];
        #pragma unroll
        for (int n = 0; n < 8; n++) {
            unsigned bb[2] = { sMg[(kb + thr) * 72 + n * 8 + grp],
                               sMg[(kb + thr + 4) * 72 + n * 8 + grp] };
            mma8(acc_o[n], a, bb);
        }
    }

    // ---- epilogue: transfer, update, clip, histories, next-step row means ----
    int op = pop[b * T_ + t];
    float insv = (op == 1) ? 1.f : 0.f;
    float trv = (op == 2) ? 1.f : 0.f;
    int cA = c0 + r0 + grp;
    int cB = cA + 8;
    float p0 = g_proj[(t * B_ + b) * C_ + cA];
    float p1 = g_proj[(t * B_ + b) * C_ + cB];
    long bcA = (long)(b * C_ + cA);
    long bcB = (long)(b * C_ + cB);
    long hA = (((long)t * B_ + b) * C_ + cA) * AT_;
    long hB = (((long)t * B_ + b) * C_ + cB) * AT_;
    float asum0 = 0.f, asum1 = 0.f;

    #pragma unroll
    for (int n = 0; n < 8; n++) {
        int col = n * 8 + thr * 2;
        float m0 = s_meta[col], m1 = s_meta[col + 1];
        float b20 = s_b2[col], b21 = s_b2[col + 1];

        // row A
        {
            float tr0 = acc_o[n][0] + b20;
            float tr1 = acc_o[n][1] + b21;
            float2 aold = *(float2*)&g_ia[bcA * 128 + ID_ + col];
            float a0 = aold.x + insv * (m0 * p0) + trv * tr0;
            float a1 = aold.y + insv * (m1 * p0) + trv * tr1;
            a0 = (a0 >= 0.f) ? a0 : 0.01f * a0;
            a1 = (a1 >= 0.f) ? a1 : 0.01f * a1;
            a0 = fminf(fmaxf(a0, -1.f), 2.f);
            a1 = fminf(fmaxf(a1, -1.f), 2.f);
            *(float2*)&g_ia[bcA * 128 + ID_ + col] = make_float2(a0, a1);
            *(float2*)&att_hist[hA + col] = make_float2(a0, a1);
            *(float2*)&trans_hist[hA + col] = make_float2(tr0, tr1);
            asum0 += a0 + a1;
        }
        // row B
        {
            float tr0 = acc_o[n][2] + b20;
            float tr1 = acc_o[n][3] + b21;
            float2 aold = *(float2*)&g_ia[bcB * 128 + ID_ + col];
            float a0 = aold.x + insv * (m0 * p1) + trv * tr0;
            float a1 = aold.y + insv * (m1 * p1) + trv * tr1;
            a0 = (a0 >= 0.f) ? a0 : 0.01f * a0;
            a1 = (a1 >= 0.f) ? a1 : 0.01f * a1;
            a0 = fminf(fmaxf(a0, -1.f), 2.f);
            a1 = fminf(fmaxf(a1, -1.f), 2.f);
            *(float2*)&g_ia[bcB * 128 + ID_ + col] = make_float2(a0, a1);
            *(float2*)&att_hist[hB + col] = make_float2(a0, a1);
            *(float2*)&trans_hist[hB + col] = make_float2(tr0, tr1);
            asum1 += a0 + a1;
        }
    }
    // reduce across the 4 threads (thr bits) that share each row
    asum0 += __shfl_xor_sync(0xffffffffu, asum0, 1);
    asum0 += __shfl_xor_sync(0xffffffffu, asum0, 2);
    asum1 += __shfl_xor_sync(0xffffffffu, asum1, 1);
    asum1 += __shfl_xor_sync(0xffffffffu, asum1, 2);
    if (thr == 0) {
        g_am[bcA] = asum0 * (1.f / (float)AT_);
        g_am[bcB] = asum1 * (1.f / (float)AT_);
    }
}

// ---------------- final log-softmax over C of mean attention ----------------
__global__ void k_final(float* __restrict__ out) {
    int b = blockIdx.x, tid = threadIdx.x;
    __shared__ float m_s[C_];
    __shared__ float red[256];
    for (int c = tid; c < C_; c += 256) m_s[c] = g_am[(long)b * C_ + c];
    __syncthreads();
    float mx = -1e30f;
    for (int c = tid; c < C_; c += 256) mx = fmaxf(mx, m_s[c]);
    red[tid] = mx;
    __syncthreads();
    for (int s = 128; s; s >>= 1) {
        if (tid < s) red[tid] = fmaxf(red[tid], red[tid + s]);
        __syncthreads();
    }
    mx = red[0];
    __syncthreads();
    float se = 0.f;
    for (int c = tid; c < C_; c += 256) se += expf(m_s[c] - mx);
    red[tid] = se;
    __syncthreads();
    for (int s = 128; s; s >>= 1) {
        if (tid < s) red[tid] += red[tid + s];
        __syncthreads();
    }
    float lse = logf(red[0]);
    __syncthreads();
    for (int c = tid; c < C_; c += 256) out[b * C_ + c] = m_s[c] - mx - lse;
}

// ---------------- launch ----------------
extern "C" void kernel_launch(void* const* d_in, const int* in_sizes, int n_in,
                              void* d_out, int out_size) {
    (void)in_sizes; (void)n_in; (void)out_size;
    const int* scene     = (const int*)d_in[0];
    const int* prog_op   = (const int*)d_in[1];
    const int* prog_arg  = (const int*)d_in[2];
    const float* aein    = (const float*)d_in[3];
    const float* aeout   = (const float*)d_in[4];
    const float* aeid    = (const float*)d_in[5];
    const float* cein    = (const float*)d_in[6];
    const float* ceout   = (const float*)d_in[7];
    const float* ceid    = (const float*)d_in[8];
    const float* att_init = (const float*)d_in[11];
    const float* axw1    = (const float*)d_in[12];
    const float* axb1    = (const float*)d_in[13];
    const float* axw2    = (const float*)d_in[14];
    const float* axb2    = (const float*)d_in[15];
    const float* mw1     = (const float*)d_in[16];
    const float* mb1     = (const float*)d_in[17];
    const float* mw2     = (const float*)d_in[18];
    const float* mb2     = (const float*)d_in[19];

    float* out = (float*)d_out;
    float* att_hist = out + B_ * C_;
    float* ins_hist = att_hist + (long)T_ * B_ * C_ * AT_;
    float* trans_hist = ins_hist + (long)T_ * B_ * C_ * AT_;

    const size_t dsm = 48640u * 4u;   // 190 KB dynamic smem for k_fused_tc
    cudaFuncSetAttribute(k_fused_tc, cudaFuncAttributeMaxDynamicSharedMemorySize, (int)dsm);

    k_wt<<<64, 256>>>(axw1, axw2);
    k_build<<<dim3(C_, B_), 128>>>(scene, aein, aeout, aeid, cein, ceout, ceid, att_init);
    k_args_meta<<<B_, 256>>>(prog_arg, prog_op, ceout, att_init, mw1, mb1, mw2, mb2);
    k_projA<<<B_ * C_ / 8, 256>>>();
    k_ins<<<(T_ * B_ * C_ * AT_) / 256, 256>>>(ins_hist);

    for (int t = 0; t < T_; t++) {
        k_tmp_tc<<<dim3(KSPLIT, B_), 256>>>();
        k_small<<<dim3(8, B_), 256>>>();
        k_fused_tc<<<dim3(C_ / 128, B_), 256, dsm>>>(t, prog_op, axb1, axb2, att_hist, trans_hist);
    }
    k_final<<<B_, 256>>>(out);
}

// round 5
// speedup vs baseline: 2.1116x; 1.0354x over previous
#include <cuda_runtime.h>

// ---------------- problem constants ----------------
constexpr int B_ = 8;
constexpr int NOBJ = 128;
constexpr int T_ = 12;
constexpr int MC = 2048;
constexpr int E_ = 128;          // EMBED_DIM
constexpr int ID_ = 64;          // IDENTITY_DIM
constexpr int AT_ = 64;          // ATTENTION_DIM
constexpr int H_ = 256;          // HIDDEN_DIM
constexpr int C_ = MC + NOBJ;    // 2176
constexpr int KSPLIT = 17;       // 2176 / 17 = 128 rows per K-chunk
constexpr unsigned NBLK = 136;   // 17 * 8 persistent blocks

// ---------------- device scratch ----------------
__device__ float g_dendron[B_ * C_ * E_];
__device__ float g_axon[B_ * C_ * E_];
__device__ float g_ia[B_ * C_ * 128];            // [0:64)=identity, [64:128)=attention (state)
__device__ float g_am[B_ * C_];                  // attention row-means for CURRENT step
__device__ float g_tmp[B_ * KSPLIT * 128 * 128]; // K-split partials
__device__ float g_M1[B_ * 128 * H_];            // (tmp @ w1^T)/C   layout [b][e][j]
__device__ float g_Mg[B_ * 128 * AT_];           // tmp[:,64:128]/C  layout [b][e][a]
__device__ float g_meta[T_ * B_ * AT_];
__device__ float g_proj[T_ * B_ * C_];
__device__ float g_args[B_ * T_ * E_];
__device__ float g_w1t[E_ * H_];                 // axon w1 transposed: [k][j]
__device__ float g_w2t[H_ * AT_];                // axon w2 transposed: [k][j]

// ---------------- software grid barrier (all blocks resident: 136 blocks, 1/SM) ----------
__device__ unsigned g_bar_count = 0;
__device__ unsigned g_bar_gen = 0;

__device__ __forceinline__ void gridsync() {
    __syncthreads();
    if (threadIdx.x == 0) {
        __threadfence();
        unsigned gen = *(volatile unsigned*)&g_bar_gen;
        if (atomicAdd(&g_bar_count, 1u) == NBLK - 1u) {
            *(volatile unsigned*)&g_bar_count = 0u;
            __threadfence();
            *(volatile unsigned*)&g_bar_gen = gen + 1u;
        } else {
            while (*(volatile unsigned*)&g_bar_gen == gen) { __nanosleep(32); }
        }
        __threadfence();
    }
    __syncthreads();
}

// ---------------- tf32 helpers ----------------
__device__ __forceinline__ unsigned f2tf(float x) {
    unsigned r;
    asm("cvt.rna.tf32.f32 %0, %1;" : "=r"(r) : "f"(x));
    return r;
}

__device__ __forceinline__ void mma8(float* d, const unsigned* a, const unsigned* b) {
    asm("mma.sync.aligned.m16n8k8.row.col.f32.tf32.tf32.f32 "
        "{%0,%1,%2,%3},{%4,%5,%6,%7},{%8,%9},{%0,%1,%2,%3};"
        : "+f"(d[0]), "+f"(d[1]), "+f"(d[2]), "+f"(d[3])
        : "r"(a[0]), "r"(a[1]), "r"(a[2]), "r"(a[3]), "r"(b[0]), "r"(b[1]));
}

// ---------------- build dendron/axon/identity + init attention + init am ----------------
__global__ void k_build(const int* __restrict__ scene,
                        const float* __restrict__ aein, const float* __restrict__ aeout,
                        const float* __restrict__ aeid,
                        const float* __restrict__ cein, const float* __restrict__ ceout,
                        const float* __restrict__ ceid,
                        const float* __restrict__ att_init) {
    int c = blockIdx.x, b = blockIdx.y, d = threadIdx.x;  // d in [0,128)
    float din, ax, idv = 0.f;
    if (c < MC) {
        din = cein[c * E_ + d];
        ax = ceout[c * E_ + d];
        if (d < ID_) idv = ceid[c * ID_ + d];
    } else {
        int o = c - MC;
        float s_in = 0.f, s_out = 0.f, s_id = 0.f;
        #pragma unroll
        for (int a = 0; a < 4; a++) {
            int idx = scene[(b * NOBJ + o) * 4 + a];
            if (idx != -1) {
                s_in += aein[(idx + 1) * E_ + d];
                s_out += aeout[(idx + 1) * E_ + d];
                if (d < ID_) s_id += aeid[(idx + 1) * ID_ + d];
            }
        }
        din = s_in; ax = s_out; idv = s_id;
    }
    long off = (long)(b * C_ + c);
    g_dendron[off * E_ + d] = din;
    g_axon[off * E_ + d] = ax;
    if (d < ID_) g_ia[off * 128 + d] = idv;
    else         g_ia[off * 128 + d] = att_init[d - ID_];
    if (d == 0) {
        float s = 0.f;
        #pragma unroll
        for (int a = 0; a < AT_; a++) s += att_init[a];
        g_am[off] = s * (1.f / (float)AT_);
    }
}

// ---------------- transpose axon MLP weights ----------------
__global__ void k_wt(const float* __restrict__ w1, const float* __restrict__ w2) {
    int tid = blockIdx.x * 256 + threadIdx.x;
    for (int i = tid; i < H_ * E_; i += gridDim.x * 256) {
        int j = i / E_, k = i % E_;
        g_w1t[k * H_ + j] = w1[i];
    }
    for (int i = tid; i < AT_ * H_; i += gridDim.x * 256) {
        int j = i / H_, k = i % H_;
        g_w2t[k * AT_ + j] = w2[i];
    }
}

// ---------------- gather arguments + meta recurrence (per-batch block) ----------------
__global__ void k_args_meta(const int* __restrict__ parg, const int* __restrict__ pop,
                            const float* __restrict__ ceout, const float* __restrict__ att_init,
                            const float* __restrict__ mw1, const float* __restrict__ mb1,
                            const float* __restrict__ mw2, const float* __restrict__ mb2) {
    int b = blockIdx.x;
    int tid = threadIdx.x;
    __shared__ float meta_s[AT_];
    __shared__ float xbuf[E_ + AT_];
    __shared__ float hbuf[H_];

    for (int i = tid; i < T_ * E_; i += 256) {
        int t = i / E_, d = i % E_;
        g_args[(b * T_ + t) * E_ + d] = ceout[parg[b * T_ + t] * E_ + d];
    }
    if (tid < AT_) meta_s[tid] = att_init[tid];
    __syncthreads();

    for (int t = 0; t < T_; t++) {
        if (tid < AT_) xbuf[tid] = meta_s[tid];
        else if (tid < AT_ + E_) xbuf[tid] = g_args[(b * T_ + t) * E_ + tid - AT_];
        __syncthreads();
        float acc = mb1[tid];
        #pragma unroll 4
        for (int k = 0; k < AT_ + E_; k++) acc += xbuf[k] * mw1[tid * (AT_ + E_) + k];
        hbuf[tid] = fmaxf(acc, 0.f);
        __syncthreads();
        if (tid < AT_) {
            float o = mb2[tid];
            #pragma unroll 4
            for (int k = 0; k < H_; k++) o += hbuf[k] * mw2[tid * H_ + k];
            float m = (pop[b * T_ + t] == 0) ? 1.f : 0.f;
            float nv = m * o + (1.f - m) * meta_s[tid];
            meta_s[tid] = nv;
            g_meta[(t * B_ + b) * AT_ + tid] = nv;
        }
        __syncthreads();
    }
}

// ---------------- proj[t,b,c] for all t at once ----------------
__global__ void k_projA() {
    __shared__ float sargs[T_ * E_];
    int blk = blockIdx.x;
    int tid = threadIdx.x;
    int row0 = blk * 8;
    int b = row0 / C_;
    for (int i = tid; i < T_ * E_; i += 256) sargs[i] = g_args[b * T_ * E_ + i];
    __syncthreads();
    int w = tid >> 5, lane = tid & 31;
    int row = row0 + w;
    int c = row % C_;
    const float* ax = &g_axon[(long)row * E_];
    float a0 = ax[lane], a1 = ax[lane + 32], a2 = ax[lane + 64], a3 = ax[lane + 96];
    #pragma unroll
    for (int t = 0; t < T_; t++) {
        float s = a0 * sargs[t * E_ + lane] + a1 * sargs[t * E_ + lane + 32]
                + a2 * sargs[t * E_ + lane + 64] + a3 * sargs[t * E_ + lane + 96];
        #pragma unroll
        for (int o = 16; o; o >>= 1) s += __shfl_xor_sync(0xffffffffu, s, o);
        if (lane == 0) g_proj[(t * B_ + b) * C_ + c] = s * (1.f / (float)E_);
    }
}

// ---------------- ins_hist (all timesteps at once) ----------------
__global__ void k_ins(float* __restrict__ out_ins) {
    int idx = blockIdx.x * 256 + threadIdx.x;
    int a = idx & (AT_ - 1);
    int rest = idx >> 6;
    int c = rest % C_;
    int tb = rest / C_;
    out_ins[idx] = g_meta[tb * AT_ + a] * g_proj[tb * C_ + c];
}

// ================= PERSISTENT step-loop kernel =================
// grid 136 = (kc 0..16) x (b 0..7); block 256; dyn smem 48640 words (190 KB):
//   sD (persistent dendron tf32): [0, 16896)   = [128][132]
//   scratch (per-phase union):    [16896, 48640)
//     tmp phase:  sA [32][136] @ +0, sB [32][136] @ +4352
//     small phase: ts [16][128] floats @ +0
//     fused phase: sM1c [128][72] @ +0, sHc [128][68] @ +9216,
//                  sW2c [64][72] @ +17920, sMg [128][72] @ +22528
//     final phase: m_s [2176] floats @ +0
__global__ void __launch_bounds__(256, 1)
k_persist(const int* __restrict__ pop,
          const float* __restrict__ b1v, const float* __restrict__ b2v,
          float* __restrict__ att_hist, float* __restrict__ trans_hist,
          float* __restrict__ out) {
    extern __shared__ unsigned smem_u[];
    unsigned* sD  = smem_u;            // persistent
    unsigned* scr = smem_u + 16896;    // phase scratch
    __shared__ float s_b1[H_];
    __shared__ float s_b2[AT_];
    __shared__ float s_meta[AT_];
    __shared__ float red[256];

    int bx = blockIdx.x;
    int kc = bx % KSPLIT, b = bx / KSPLIT;
    int tid = threadIdx.x, w = tid >> 5, lane = tid & 31;
    int grp = lane >> 2, thr = lane & 3;
    int c0 = kc * 128;
    int r0 = w * 16;

    // ---- one-time staging: dendron tile (tf32), biases ----
    for (int i = tid; i < 128 * 32; i += 256) {
        int r = i >> 5, q = (i & 31) * 4;
        float4 v = *(const float4*)&g_dendron[((long)(b * C_ + c0 + r)) * E_ + q];
        unsigned* p = &sD[r * 132 + q];
        p[0] = f2tf(v.x); p[1] = f2tf(v.y); p[2] = f2tf(v.z); p[3] = f2tf(v.w);
    }
    s_b1[tid] = b1v[tid];
    if (tid < AT_) s_b2[tid] = b2v[tid];
    int op = pop[b * T_];   // refreshed per step below

    for (int t = 0; t < T_; t++) {
        // ======== phase 1: tmp partial (tf32 MMA over this block's 128 C-rows) ========
        {
            unsigned* sA  = scr;            // [32][136]
            unsigned* sBt = scr + 4352;     // [32][136]
            float acc[16][4];
            #pragma unroll
            for (int n = 0; n < 16; n++)
                #pragma unroll
                for (int q = 0; q < 4; q++) acc[n][q] = 0.f;

            for (int it = 0; it < 4; it++) {
                __syncthreads();
                for (int i = tid; i < 32 * 32; i += 256) {
                    int r = i >> 5, q = (i & 31) * 4;
                    int c = c0 + it * 32 + r;
                    long base = (long)(b * C_ + c);
                    float amv = g_am[base];
                    float4 av = *(const float4*)&g_axon[base * E_ + q];
                    sA[r * 136 + q + 0] = f2tf(av.x * amv);
                    sA[r * 136 + q + 1] = f2tf(av.y * amv);
                    sA[r * 136 + q + 2] = f2tf(av.z * amv);
                    sA[r * 136 + q + 3] = f2tf(av.w * amv);
                    float4 bv = *(const float4*)&g_ia[base * 128 + q];
                    sBt[r * 136 + q + 0] = f2tf(bv.x);
                    sBt[r * 136 + q + 1] = f2tf(bv.y);
                    sBt[r * 136 + q + 2] = f2tf(bv.z);
                    sBt[r * 136 + q + 3] = f2tf(bv.w);
                }
                __syncthreads();
                #pragma unroll
                for (int ks = 0; ks < 4; ks++) {
                    int kb = ks * 8;
                    unsigned a[4];
                    a[0] = sA[(kb + thr) * 136 + r0 + grp];
                    a[1] = sA[(kb + thr) * 136 + r0 + grp + 8];
                    a[2] = sA[(kb + thr + 4) * 136 + r0 + grp];
                    a[3] = sA[(kb + thr + 4) * 136 + r0 + grp + 8];
                    #pragma unroll
                    for (int n = 0; n < 16; n++) {
                        unsigned bb[2] = { sBt[(kb + thr) * 136 + n * 8 + grp],
                                           sBt[(kb + thr + 4) * 136 + n * 8 + grp] };
                        mma8(acc[n], a, bb);
                    }
                }
            }
            float* o = &g_tmp[(long)(b * KSPLIT + kc) * 16384];
            #pragma unroll
            for (int n = 0; n < 16; n++) {
                int col = n * 8 + thr * 2;
                *(float2*)&o[(r0 + grp) * 128 + col]     = make_float2(acc[n][0], acc[n][1]);
                *(float2*)&o[(r0 + grp + 8) * 128 + col] = make_float2(acc[n][2], acc[n][3]);
            }
        }
        gridsync();

        // ======== phase 2: M1 = tmpsum @ w1^T / C ; Mg = tmpsum[:,64:128)/C (64 blocks) ====
        if (bx < 64) {
            int bb = bx >> 3;
            int er0 = (bx & 7) * 16;
            float* ts = (float*)scr;   // [16][128]
            for (int i = tid; i < 16 * 128; i += 256) {
                int r = i >> 7, k = i & 127;
                long base = (long)bb * KSPLIT * 16384 + (er0 + r) * 128 + k;
                float s = 0.f;
                #pragma unroll
                for (int p = 0; p < KSPLIT; p++) s += g_tmp[base + (long)p * 16384];
                ts[r * 128 + k] = s;
            }
            __syncthreads();
            const float sc = 1.f / (float)C_;
            int j = tid;
            float acc[16];
            #pragma unroll
            for (int r = 0; r < 16; r++) acc[r] = 0.f;
            for (int k = 0; k < 128; k++) {
                float wv = g_w1t[k * H_ + j];
                #pragma unroll
                for (int r = 0; r < 16; r++) acc[r] += ts[r * 128 + k] * wv;
            }
            #pragma unroll
            for (int r = 0; r < 16; r++)
                g_M1[((long)bb * 128 + er0 + r) * H_ + j] = acc[r] * sc;
            for (int i = tid; i < 16 * AT_; i += 256) {
                int r = i >> 6, a = i & 63;
                g_Mg[((long)bb * 128 + er0 + r) * AT_ + a] = ts[r * 128 + ID_ + a] * sc;
            }
        }
        gridsync();

        // ======== phase 3: fused MLP + update + histories + next-step row-means ========
        {
            unsigned* sM1c = scr;             // [128][72]
            unsigned* sHc  = scr + 9216;      // [128][68]
            unsigned* sW2c = scr + 17920;     // [64][72]
            unsigned* sMg  = scr + 22528;     // [128][72]

            for (int i = tid; i < 128 * 16; i += 256) {
                int r = i >> 4, q = (i & 15) * 4;
                float4 v = *(const float4*)&g_Mg[((long)b * 128 + r) * AT_ + q];
                unsigned* p = &sMg[r * 72 + q];
                p[0] = f2tf(v.x); p[1] = f2tf(v.y); p[2] = f2tf(v.z); p[3] = f2tf(v.w);
            }
            if (tid < AT_) s_meta[tid] = g_meta[(t * B_ + b) * AT_ + tid];
            op = pop[b * T_ + t];

            float acc_o[8][4];
            #pragma unroll
            for (int n = 0; n < 8; n++)
                #pragma unroll
                for (int q = 0; q < 4; q++) acc_o[n][q] = 0.f;

            for (int nc = 0; nc < 4; nc++) {
                __syncthreads();
                for (int i = tid; i < 128 * 16; i += 256) {
                    int r = i >> 4, q = (i & 15) * 4;
                    float4 v = *(const float4*)&g_M1[((long)b * 128 + r) * H_ + nc * 64 + q];
                    unsigned* p = &sM1c[r * 72 + q];
                    p[0] = f2tf(v.x); p[1] = f2tf(v.y); p[2] = f2tf(v.z); p[3] = f2tf(v.w);
                }
                for (int i = tid; i < 64 * 16; i += 256) {
                    int r = i >> 4, q = (i & 15) * 4;
                    float4 v = *(const float4*)&g_w2t[(nc * 64 + r) * AT_ + q];
                    unsigned* p = &sW2c[r * 72 + q];
                    p[0] = f2tf(v.x); p[1] = f2tf(v.y); p[2] = f2tf(v.z); p[3] = f2tf(v.w);
                }
                __syncthreads();

                // layer 1: 16 rows x 64 cols per warp, K = 128
                float acc_h[8][4];
                #pragma unroll
                for (int n = 0; n < 8; n++)
                    #pragma unroll
                    for (int q = 0; q < 4; q++) acc_h[n][q] = 0.f;
                #pragma unroll
                for (int ks = 0; ks < 16; ks++) {
                    int kb = ks * 8;
                    unsigned a[4];
                    a[0] = sD[(r0 + grp) * 132 + kb + thr];
                    a[1] = sD[(r0 + grp + 8) * 132 + kb + thr];
                    a[2] = sD[(r0 + grp) * 132 + kb + thr + 4];
                    a[3] = sD[(r0 + grp + 8) * 132 + kb + thr + 4];
                    #pragma unroll
                    for (int n = 0; n < 8; n++) {
                        unsigned bb[2] = { sM1c[(kb + thr) * 72 + n * 8 + grp],
                                           sM1c[(kb + thr + 4) * 72 + n * 8 + grp] };
                        mma8(acc_h[n], a, bb);
                    }
                }
                #pragma unroll
                for (int n = 0; n < 8; n++) {
                    int col = n * 8 + thr * 2;
                    float bias0 = s_b1[nc * 64 + col], bias1 = s_b1[nc * 64 + col + 1];
                    sHc[(r0 + grp) * 68 + col]         = f2tf(fmaxf(acc_h[n][0] + bias0, 0.f));
                    sHc[(r0 + grp) * 68 + col + 1]     = f2tf(fmaxf(acc_h[n][1] + bias1, 0.f));
                    sHc[(r0 + grp + 8) * 68 + col]     = f2tf(fmaxf(acc_h[n][2] + bias0, 0.f));
                    sHc[(r0 + grp + 8) * 68 + col + 1] = f2tf(fmaxf(acc_h[n][3] + bias1, 0.f));
                }
                __syncthreads();

                // layer 2 partial: K = 64
                #pragma unroll
                for (int ks = 0; ks < 8; ks++) {
                    int kb = ks * 8;
                    unsigned a[4];
                    a[0] = sHc[(r0 + grp) * 68 + kb + thr];
                    a[1] = sHc[(r0 + grp + 8) * 68 + kb + thr];
                    a[2] = sHc[(r0 + grp) * 68 + kb + thr + 4];
                    a[3] = sHc[(r0 + grp + 8) * 68 + kb + thr + 4];
                    #pragma unroll
                    for (int n = 0; n < 8; n++) {
                        unsigned bb[2] = { sW2c[(kb + thr) * 72 + n * 8 + grp],
                                           sW2c[(kb + thr + 4) * 72 + n * 8 + grp] };
                        mma8(acc_o[n], a, bb);
                    }
                }
            }

            // residual: d @ Mg, K = 128
            #pragma unroll
            for (int ks = 0; ks < 16; ks++) {
                int kb = ks * 8;
                unsigned a[4];
                a[0] = sD[(r0 + grp) * 132 + kb + thr];
                a[1] = sD[(r0 + grp + 8) * 132 + kb + thr];
                a[2] = sD[(r0 + grp) * 132 + kb + thr + 4];
                a[3] = sD[(r0 + grp + 8) * 132 + kb + thr + 4];
                #pragma unroll
                for (int n = 0; n < 8; n++) {
                    unsigned bb[2] = { sMg[(kb + thr) * 72 + n * 8 + grp],
                                       sMg[(kb + thr + 4) * 72 + n * 8 + grp] };
                    mma8(acc_o[n], a, bb);
                }
            }

            // epilogue
            float insv = (op == 1) ? 1.f : 0.f;
            float trv = (op == 2) ? 1.f : 0.f;
            int cA = c0 + r0 + grp;
            int cB = cA + 8;
            float p0 = g_proj[(t * B_ + b) * C_ + cA];
            float p1 = g_proj[(t * B_ + b) * C_ + cB];
            long bcA = (long)(b * C_ + cA);
            long bcB = (long)(b * C_ + cB);
            long hA = (((long)t * B_ + b) * C_ + cA) * AT_;
            long hB = (((long)t * B_ + b) * C_ + cB) * AT_;
            float asum0 = 0.f, asum1 = 0.f;

            #pragma unroll
            for (int n = 0; n < 8; n++) {
                int col = n * 8 + thr * 2;
                float m0 = s_meta[col], m1 = s_meta[col + 1];
                float b20 = s_b2[col], b21 = s_b2[col + 1];
                {
                    float tr0 = acc_o[n][0] + b20;
                    float tr1 = acc_o[n][1] + b21;
                    float2 aold = *(float2*)&g_ia[bcA * 128 + ID_ + col];
                    float a0 = aold.x + insv * (m0 * p0) + trv * tr0;
                    float a1 = aold.y + insv * (m1 * p0) + trv * tr1;
                    a0 = (a0 >= 0.f) ? a0 : 0.01f * a0;
                    a1 = (a1 >= 0.f) ? a1 : 0.01f * a1;
                    a0 = fminf(fmaxf(a0, -1.f), 2.f);
                    a1 = fminf(fmaxf(a1, -1.f), 2.f);
                    *(float2*)&g_ia[bcA * 128 + ID_ + col] = make_float2(a0, a1);
                    *(float2*)&att_hist[hA + col] = make_float2(a0, a1);
                    *(float2*)&trans_hist[hA + col] = make_float2(tr0, tr1);
                    asum0 += a0 + a1;
                }
                {
                    float tr0 = acc_o[n][2] + b20;
                    float tr1 = acc_o[n][3] + b21;
                    float2 aold = *(float2*)&g_ia[bcB * 128 + ID_ + col];
                    float a0 = aold.x + insv * (m0 * p1) + trv * tr0;
                    float a1 = aold.y + insv * (m1 * p1) + trv * tr1;
                    a0 = (a0 >= 0.f) ? a0 : 0.01f * a0;
                    a1 = (a1 >= 0.f) ? a1 : 0.01f * a1;
                    a0 = fminf(fmaxf(a0, -1.f), 2.f);
                    a1 = fminf(fmaxf(a1, -1.f), 2.f);
                    *(float2*)&g_ia[bcB * 128 + ID_ + col] = make_float2(a0, a1);
                    *(float2*)&att_hist[hB + col] = make_float2(a0, a1);
                    *(float2*)&trans_hist[hB + col] = make_float2(tr0, tr1);
                    asum1 += a0 + a1;
                }
            }
            asum0 += __shfl_xor_sync(0xffffffffu, asum0, 1);
            asum0 += __shfl_xor_sync(0xffffffffu, asum0, 2);
            asum1 += __shfl_xor_sync(0xffffffffu, asum1, 1);
            asum1 += __shfl_xor_sync(0xffffffffu, asum1, 2);
            if (thr == 0) {
                g_am[bcA] = asum0 * (1.f / (float)AT_);
                g_am[bcB] = asum1 * (1.f / (float)AT_);
            }
        }
        gridsync();
    }

    // ======== final: log-softmax over C of mean attention (blocks 0..7) ========
    if (bx < B_) {
        int bb = bx;
        float* m_s = (float*)scr;   // 2176 floats
        for (int c = tid; c < C_; c += 256) m_s[c] = g_am[(long)bb * C_ + c];
        __syncthreads();
        float mx = -1e30f;
        for (int c = tid; c < C_; c += 256) mx = fmaxf(mx, m_s[c]);
        red[tid] = mx;
        __syncthreads();
        for (int s = 128; s; s >>= 1) {
            if (tid < s) red[tid] = fmaxf(red[tid], red[tid + s]);
            __syncthreads();
        }
        mx = red[0];
        __syncthreads();
        float se = 0.f;
        for (int c = tid; c < C_; c += 256) se += expf(m_s[c] - mx);
        red[tid] = se;
        __syncthreads();
        for (int s = 128; s; s >>= 1) {
            if (tid < s) red[tid] += red[tid + s];
            __syncthreads();
        }
        float lse = logf(red[0]);
        __syncthreads();
        for (int c = tid; c < C_; c += 256) out[bb * C_ + c] = m_s[c] - mx - lse;
    }
}

// ---------------- launch ----------------
extern "C" void kernel_launch(void* const* d_in, const int* in_sizes, int n_in,
                              void* d_out, int out_size) {
    (void)in_sizes; (void)n_in; (void)out_size;
    const int* scene     = (const int*)d_in[0];
    const int* prog_op   = (const int*)d_in[1];
    const int* prog_arg  = (const int*)d_in[2];
    const float* aein    = (const float*)d_in[3];
    const float* aeout   = (const float*)d_in[4];
    const float* aeid    = (const float*)d_in[5];
    const float* cein    = (const float*)d_in[6];
    const float* ceout   = (const float*)d_in[7];
    const float* ceid    = (const float*)d_in[8];
    const float* att_init = (const float*)d_in[11];
    const float* axw1    = (const float*)d_in[12];
    const float* axb1    = (const float*)d_in[13];
    const float* axw2    = (const float*)d_in[14];
    const float* axb2    = (const float*)d_in[15];
    const float* mw1     = (const float*)d_in[16];
    const float* mb1     = (const float*)d_in[17];
    const float* mw2     = (const float*)d_in[18];
    const float* mb2     = (const float*)d_in[19];

    float* out = (float*)d_out;
    float* att_hist = out + B_ * C_;
    float* ins_hist = att_hist + (long)T_ * B_ * C_ * AT_;
    float* trans_hist = ins_hist + (long)T_ * B_ * C_ * AT_;

    const size_t dsm = 48640u * 4u;   // 190 KB dynamic smem
    cudaFuncSetAttribute(k_persist, cudaFuncAttributeMaxDynamicSharedMemorySize, (int)dsm);

    k_wt<<<64, 256>>>(axw1, axw2);
    k_build<<<dim3(C_, B_), 128>>>(scene, aein, aeout, aeid, cein, ceout, ceid, att_init);
    k_args_meta<<<B_, 256>>>(prog_arg, prog_op, ceout, att_init, mw1, mb1, mw2, mb2);
    k_projA<<<B_ * C_ / 8, 256>>>();
    k_ins<<<(T_ * B_ * C_ * AT_) / 256, 256>>>(ins_hist);

    k_persist<<<NBLK, 256, dsm>>>(prog_op, axb1, axb2, att_hist, trans_hist, out);
}